// round 2
// baseline (speedup 1.0000x reference)
#include <cuda_runtime.h>
#include <cuda_bf16.h>
#include <math.h>

#define N_NODES 100000
#define E_IN    1600000
#define E_TOT   (E_IN + N_NODES)
#define F_IN    256
#define H1      8
#define F1      8
#define C1      64      /* H1*F1 */
#define C2      40      /* classes */

// ---------------- scratch (static device globals; no allocation) ----------------
__device__ float g_h1 [(size_t)N_NODES * C1];   // layer-1 linear output (pre-activation)
__device__ float g_as1[(size_t)N_NODES * H1];
__device__ float g_ad1[(size_t)N_NODES * H1];
__device__ float g_x2 [(size_t)N_NODES * C1];   // elu(agg1 + bias1)
__device__ float g_h2 [(size_t)N_NODES * C2];
__device__ float g_as2[N_NODES];
__device__ float g_ad2[N_NODES];
__device__ int   g_deg[N_NODES];
__device__ int   g_cur[N_NODES];
__device__ int   g_off[N_NODES + 1];
__device__ int   g_csr[E_TOT];

// ---------------- CSR build ----------------
__global__ void zero_kernel() {
    int i = blockIdx.x * blockDim.x + threadIdx.x;
    if (i < N_NODES) { g_deg[i] = 0; g_cur[i] = 0; }
}

__global__ void hist_kernel(const int* __restrict__ ei) {
    int i = blockIdx.x * blockDim.x + threadIdx.x;
    if (i >= E_TOT) return;
    int d = (i < E_IN) ? ei[E_IN + i] : (i - E_IN);
    atomicAdd(&g_deg[d], 1);
}

__global__ void scan_kernel() {
    __shared__ int sums[1024];
    int t = threadIdx.x;
    const int SEG = (N_NODES + 1023) / 1024;
    int b = t * SEG;
    int e = b + SEG; if (e > N_NODES) e = N_NODES;
    int s = 0;
    for (int i = b; i < e; i++) s += g_deg[i];
    sums[t] = s;
    __syncthreads();
    for (int o = 1; o < 1024; o <<= 1) {
        int v = (t >= o) ? sums[t - o] : 0;
        __syncthreads();
        if (t >= o) sums[t] += v;
        __syncthreads();
    }
    int run = (t == 0) ? 0 : sums[t - 1];
    for (int i = b; i < e; i++) { g_off[i] = run; run += g_deg[i]; }
    if (t == 0) g_off[N_NODES] = E_TOT;
}

__global__ void scatter_kernel(const int* __restrict__ ei) {
    int i = blockIdx.x * blockDim.x + threadIdx.x;
    if (i >= E_TOT) return;
    int d, s;
    if (i < E_IN) { s = ei[i]; d = ei[E_IN + i]; }
    else          { s = i - E_IN; d = i - E_IN; }
    int p = g_off[d] + atomicAdd(&g_cur[d], 1);
    g_csr[p] = s;
}

// ---------------- GEMM1: g_h1 = x @ W1, fused attention logits ----------------
// 256 threads (16x16), 64-row x 64-col tile, K-tile 32.
__global__ void gemm1_kernel(const float* __restrict__ x, const float* __restrict__ W1,
                             const float* __restrict__ a_s, const float* __restrict__ a_d) {
    __shared__ float Xs[64][36];
    __shared__ float Ws[32][64];
    int tid = threadIdx.x;
    int tx = tid & 15, ty = tid >> 4;
    int row0 = blockIdx.x * 64;
    float acc[4][4];
#pragma unroll
    for (int i = 0; i < 4; i++)
#pragma unroll
        for (int j = 0; j < 4; j++) acc[i][j] = 0.f;

    for (int kt = 0; kt < F_IN; kt += 32) {
#pragma unroll
        for (int i = 0; i < 2; i++) {
            int idx = tid + i * 256;        // 512 float4s for the X tile
            int r = idx >> 3, q = idx & 7;
            int gr = row0 + r;
            float4 v = make_float4(0.f, 0.f, 0.f, 0.f);
            if (gr < N_NODES) v = *(const float4*)&x[(size_t)gr * F_IN + kt + q * 4];
            Xs[r][q * 4 + 0] = v.x; Xs[r][q * 4 + 1] = v.y;
            Xs[r][q * 4 + 2] = v.z; Xs[r][q * 4 + 3] = v.w;
        }
#pragma unroll
        for (int i = 0; i < 2; i++) {
            int idx = tid + i * 256;        // 512 float4s for the W tile
            int r = idx >> 4, q = idx & 15;
            *(float4*)&Ws[r][q * 4] = *(const float4*)&W1[(size_t)(kt + r) * C1 + q * 4];
        }
        __syncthreads();
#pragma unroll
        for (int k = 0; k < 32; k++) {
            float4 b = *(float4*)&Ws[k][tx * 4];
#pragma unroll
            for (int i = 0; i < 4; i++) {
                float a = Xs[ty * 4 + i][k];
                acc[i][0] += a * b.x; acc[i][1] += a * b.y;
                acc[i][2] += a * b.z; acc[i][3] += a * b.w;
            }
        }
        __syncthreads();
    }

    int n0 = tx * 4;
    float asw[4], adw[4];
#pragma unroll
    for (int j = 0; j < 4; j++) { asw[j] = a_s[n0 + j]; adw[j] = a_d[n0 + j]; }

#pragma unroll
    for (int i = 0; i < 4; i++) {
        int r = row0 + ty * 4 + i;
        float ps = acc[i][0]*asw[0] + acc[i][1]*asw[1] + acc[i][2]*asw[2] + acc[i][3]*asw[3];
        float pd = acc[i][0]*adw[0] + acc[i][1]*adw[1] + acc[i][2]*adw[2] + acc[i][3]*adw[3];
        ps += __shfl_xor_sync(0xffffffffu, ps, 1);
        pd += __shfl_xor_sync(0xffffffffu, pd, 1);
        if (r < N_NODES) {
            float4 c = make_float4(acc[i][0], acc[i][1], acc[i][2], acc[i][3]);
            *(float4*)&g_h1[(size_t)r * C1 + n0] = c;
            if ((tx & 1) == 0) {
                g_as1[r * H1 + (tx >> 1)] = ps;
                g_ad1[r * H1 + (tx >> 1)] = pd;
            }
        }
    }
}

// ---------------- Aggregation layer 1 (warp per dst node) ----------------
__global__ void agg1_kernel(const float* __restrict__ bias1) {
    int gw = (blockIdx.x * blockDim.x + threadIdx.x) >> 5;
    int lane = threadIdx.x & 31;
    if (gw >= N_NODES) return;
    int n = gw;
    int start = g_off[n], end = g_off[n + 1];

    float adv = (lane < H1) ? g_ad1[n * H1 + lane] : 0.f;
    float adr[H1];
#pragma unroll
    for (int h = 0; h < H1; h++) adr[h] = __shfl_sync(0xffffffffu, adv, h);

    // pass 1: per-head max (lane-parallel over edges)
    float mx[H1];
#pragma unroll
    for (int h = 0; h < H1; h++) mx[h] = -INFINITY;
    for (int e = start + lane; e < end; e += 32) {
        int s = g_csr[e];
        const float* asp = &g_as1[s * H1];
#pragma unroll
        for (int h = 0; h < H1; h++) {
            float v = asp[h] + adr[h];
            v = v > 0.f ? v : 0.2f * v;
            mx[h] = fmaxf(mx[h], v);
        }
    }
#pragma unroll
    for (int h = 0; h < H1; h++)
#pragma unroll
        for (int o = 16; o > 0; o >>= 1)
            mx[h] = fmaxf(mx[h], __shfl_xor_sync(0xffffffffu, mx[h], o));

    float m_lane = (lane < H1) ? mx[lane] : 0.f;

    // pass 2: edge-serial, lanes split 64 features (lane, lane+32).
    // Prefetch the next source index so the g_csr load latency is off the
    // critical path (dependency chain becomes h1-load -> FMA only).
    float accA = 0.f, accB = 0.f, denom = 0.f;
    int hA = lane >> 3, hB = (lane >> 3) + 4;
    int s = (start < end) ? g_csr[start] : 0;
    for (int e = start; e < end; e++) {
        int s_next = (e + 1 < end) ? g_csr[e + 1] : 0;
        float w = 0.f;
        if (lane < H1) {
            float v = g_as1[s * H1 + lane] + adv;
            v = v > 0.f ? v : 0.2f * v;
            w = expf(v - m_lane);
            denom += w;
        }
        float wA = __shfl_sync(0xffffffffu, w, hA);
        float wB = __shfl_sync(0xffffffffu, w, hB);
        const float* hp = &g_h1[(size_t)s * C1];
        accA += wA * hp[lane];
        accB += wB * hp[lane + 32];
        s = s_next;
    }
    float dA = __shfl_sync(0xffffffffu, denom, hA) + 1e-16f;
    float dB = __shfl_sync(0xffffffffu, denom, hB) + 1e-16f;
    float oA = accA / dA + bias1[lane];
    float oB = accB / dB + bias1[lane + 32];
    oA = oA > 0.f ? oA : expm1f(oA);
    oB = oB > 0.f ? oB : expm1f(oB);
    g_x2[(size_t)n * C1 + lane]      = oA;
    g_x2[(size_t)n * C1 + 32 + lane] = oB;
}

// ---------------- GEMM2: g_h2 = g_x2 @ W2, fused layer-2 attention logits ----------------
// 256 threads, 64 nodes per block; thread = (node = tid>>2, 10 cols).
__global__ void gemm2_kernel(const float* __restrict__ W2,
                             const float* __restrict__ a_s2, const float* __restrict__ a_d2) {
    __shared__ float Xs[64][68];
    __shared__ float Ws[C1][C2];
    int tid = threadIdx.x;
    int node = tid >> 2, cg = tid & 3, c0 = cg * 10;
    int n0 = blockIdx.x * 64;

    for (int i = tid; i < C1 * C2; i += 256) Ws[i / C2][i % C2] = W2[i];
#pragma unroll
    for (int i = 0; i < 4; i++) {
        int idx = tid + i * 256;            // 1024 float4s
        int r = idx >> 4, q = idx & 15;
        int gr = n0 + r;
        float4 v = make_float4(0.f, 0.f, 0.f, 0.f);
        if (gr < N_NODES) v = *(const float4*)&g_x2[(size_t)gr * C1 + q * 4];
        Xs[r][q * 4 + 0] = v.x; Xs[r][q * 4 + 1] = v.y;
        Xs[r][q * 4 + 2] = v.z; Xs[r][q * 4 + 3] = v.w;
    }
    __syncthreads();

    float acc[10];
#pragma unroll
    for (int j = 0; j < 10; j++) acc[j] = 0.f;
    int gn = n0 + node;
    if (gn < N_NODES) {
#pragma unroll
        for (int k = 0; k < C1; k++) {
            float a = Xs[node][k];
#pragma unroll
            for (int j = 0; j < 10; j++) acc[j] += a * Ws[k][c0 + j];
        }
    }
    float ps = 0.f, pd = 0.f;
    if (gn < N_NODES) {
#pragma unroll
        for (int j = 0; j < 10; j++) {
            g_h2[(size_t)gn * C2 + c0 + j] = acc[j];
            ps += acc[j] * a_s2[c0 + j];
            pd += acc[j] * a_d2[c0 + j];
        }
    }
    ps += __shfl_xor_sync(0xffffffffu, ps, 1);
    ps += __shfl_xor_sync(0xffffffffu, ps, 2);
    pd += __shfl_xor_sync(0xffffffffu, pd, 1);
    pd += __shfl_xor_sync(0xffffffffu, pd, 2);
    if (gn < N_NODES && cg == 0) { g_as2[gn] = ps; g_ad2[gn] = pd; }
}

// ---------------- Aggregation layer 2 + log_softmax (warp per dst node) ----------------
__global__ void agg2_kernel(const float* __restrict__ bias2, float* __restrict__ out) {
    int gw = (blockIdx.x * blockDim.x + threadIdx.x) >> 5;
    int lane = threadIdx.x & 31;
    if (gw >= N_NODES) return;
    int n = gw;
    int start = g_off[n], end = g_off[n + 1];
    float adv = g_ad2[n];

    float mx = -INFINITY;
    for (int e = start + lane; e < end; e += 32) {
        int s = g_csr[e];
        float v = g_as2[s] + adv;
        v = v > 0.f ? v : 0.2f * v;
        mx = fmaxf(mx, v);
    }
#pragma unroll
    for (int o = 16; o > 0; o >>= 1)
        mx = fmaxf(mx, __shfl_xor_sync(0xffffffffu, mx, o));

    // edge-serial pass with index prefetch (same pipelining as agg1)
    float acc0 = 0.f, acc1 = 0.f, denom = 0.f;
    int s = (start < end) ? g_csr[start] : 0;
    for (int e = start; e < end; e++) {
        int s_next = (e + 1 < end) ? g_csr[e + 1] : 0;
        float v = g_as2[s] + adv;
        v = v > 0.f ? v : 0.2f * v;
        float w = expf(v - mx);
        denom += w;
        const float* hp = &g_h2[(size_t)s * C2];
        acc0 += w * hp[lane];
        if (lane < 8) acc1 += w * hp[32 + lane];
        s = s_next;
    }
    float d = denom + 1e-16f;
    float r0 = acc0 / d + bias2[lane];
    float r1 = (lane < 8) ? (acc1 / d + bias2[32 + lane]) : -INFINITY;

    float mm = fmaxf(r0, r1);
#pragma unroll
    for (int o = 16; o > 0; o >>= 1)
        mm = fmaxf(mm, __shfl_xor_sync(0xffffffffu, mm, o));
    float ss = expf(r0 - mm) + ((lane < 8) ? expf(r1 - mm) : 0.f);
#pragma unroll
    for (int o = 16; o > 0; o >>= 1)
        ss += __shfl_xor_sync(0xffffffffu, ss, o);
    float lse = logf(ss);

    out[(size_t)n * C2 + lane] = r0 - mm - lse;
    if (lane < 8) out[(size_t)n * C2 + 32 + lane] = r1 - mm - lse;
}

// ---------------- launch ----------------
extern "C" void kernel_launch(void* const* d_in, const int* in_sizes, int n_in,
                              void* d_out, int out_size) {
    const float* x     = (const float*)d_in[0];
    const int*   ei    = (const int*)  d_in[1];
    const float* W1    = (const float*)d_in[2];
    const float* as1   = (const float*)d_in[3];
    const float* ad1   = (const float*)d_in[4];
    const float* b1    = (const float*)d_in[5];
    const float* W2    = (const float*)d_in[6];
    const float* as2   = (const float*)d_in[7];
    const float* ad2   = (const float*)d_in[8];
    const float* b2    = (const float*)d_in[9];
    float* out = (float*)d_out;

    (void)in_sizes; (void)n_in; (void)out_size;

    zero_kernel   <<<(N_NODES + 255) / 256, 256>>>();
    hist_kernel   <<<(E_TOT + 255) / 256, 256>>>(ei);
    scan_kernel   <<<1, 1024>>>();
    scatter_kernel<<<(E_TOT + 255) / 256, 256>>>(ei);

    gemm1_kernel  <<<(N_NODES + 63) / 64, 256>>>(x, W1, as1, ad1);
    agg1_kernel   <<<(N_NODES * 32 + 255) / 256, 256>>>(b1);
    gemm2_kernel  <<<(N_NODES + 63) / 64, 256>>>(W2, as2, ad2);
    agg2_kernel   <<<(N_NODES * 32 + 255) / 256, 256>>>(b2, out);
}

// round 4
// speedup vs baseline: 1.0270x; 1.0270x over previous
#include <cuda_runtime.h>
#include <cuda_bf16.h>
#include <math.h>

#define N_NODES 100000
#define E_IN    1600000
#define E_TOT   (E_IN + N_NODES)
#define F_IN    256
#define H1      8
#define C1      64      /* H1*F1 */
#define C2      40      /* classes */

// ---------------- scratch (static device globals; no allocation) ----------------
__device__ float g_h1 [(size_t)N_NODES * C1];
__device__ float g_as1[(size_t)N_NODES * H1];
__device__ float g_ad1[(size_t)N_NODES * H1];
__device__ float g_x2 [(size_t)N_NODES * C1];
__device__ float g_h2 [(size_t)N_NODES * C2];
__device__ float g_as2[N_NODES];
__device__ float g_ad2[N_NODES];
__device__ int   g_deg[N_NODES];
__device__ int   g_cur[N_NODES];
__device__ int   g_off[N_NODES + 1];
__device__ int   g_csr[E_TOT];

// ---------------- CSR build ----------------
__global__ void zero_kernel() {
    int i = blockIdx.x * blockDim.x + threadIdx.x;
    if (i < N_NODES) { g_deg[i] = 0; g_cur[i] = 0; }
}

__global__ void hist_kernel(const int* __restrict__ ei) {
    int i = blockIdx.x * blockDim.x + threadIdx.x;
    if (i >= E_TOT) return;
    int d = (i < E_IN) ? ei[E_IN + i] : (i - E_IN);
    atomicAdd(&g_deg[d], 1);
}

__global__ void scan_kernel() {
    __shared__ int sums[1024];
    int t = threadIdx.x;
    const int SEG = (N_NODES + 1023) / 1024;
    int b = t * SEG;
    int e = b + SEG; if (e > N_NODES) e = N_NODES;
    int s = 0;
    for (int i = b; i < e; i++) s += g_deg[i];
    sums[t] = s;
    __syncthreads();
    for (int o = 1; o < 1024; o <<= 1) {
        int v = (t >= o) ? sums[t - o] : 0;
        __syncthreads();
        if (t >= o) sums[t] += v;
        __syncthreads();
    }
    int run = (t == 0) ? 0 : sums[t - 1];
    for (int i = b; i < e; i++) { g_off[i] = run; run += g_deg[i]; }
    if (t == 0) g_off[N_NODES] = E_TOT;
}

__global__ void scatter_kernel(const int* __restrict__ ei) {
    int i = blockIdx.x * blockDim.x + threadIdx.x;
    if (i >= E_TOT) return;
    int d, s;
    if (i < E_IN) { s = ei[i]; d = ei[E_IN + i]; }
    else          { s = i - E_IN; d = i - E_IN; }
    int p = g_off[d] + atomicAdd(&g_cur[d], 1);
    g_csr[p] = s;
}

// ---------------- GEMM1: g_h1 = x @ W1, fused attention logits ----------------
// 256 threads, 128x64 tile, K-tile 32, 4x8 micro-tile.
// tx = col group of 8 (== head index), ty = row group of 4.
__global__ void __launch_bounds__(256) gemm1_kernel(
        const float* __restrict__ x, const float* __restrict__ W1,
        const float* __restrict__ a_s, const float* __restrict__ a_d) {
    __shared__ float Xs[128][33];
    __shared__ float Ws[32][64];
    int tid = threadIdx.x;
    int tx = tid & 7;
    int ty = tid >> 3;
    int row0 = blockIdx.x * 128;

    float acc[4][8];
#pragma unroll
    for (int i = 0; i < 4; i++)
#pragma unroll
        for (int j = 0; j < 8; j++) acc[i][j] = 0.f;

    float4 xbuf[4];
    float4 wbuf[2];
    // prefetch K-tile 0
#pragma unroll
    for (int i = 0; i < 4; i++) {
        int idx = tid + i * 256; int r = idx >> 3, q = idx & 7;
        int gr = row0 + r;
        xbuf[i] = (gr < N_NODES) ? *(const float4*)&x[(size_t)gr * F_IN + q * 4]
                                 : make_float4(0.f, 0.f, 0.f, 0.f);
    }
#pragma unroll
    for (int i = 0; i < 2; i++) {
        int idx = tid + i * 256; int r = idx >> 4, q = idx & 15;
        wbuf[i] = *(const float4*)&W1[(size_t)r * C1 + q * 4];
    }

    for (int kt = 0; kt < F_IN; kt += 32) {
        // commit buffered tile to shared
#pragma unroll
        for (int i = 0; i < 4; i++) {
            int idx = tid + i * 256; int r = idx >> 3, q = idx & 7;
            Xs[r][q * 4 + 0] = xbuf[i].x; Xs[r][q * 4 + 1] = xbuf[i].y;
            Xs[r][q * 4 + 2] = xbuf[i].z; Xs[r][q * 4 + 3] = xbuf[i].w;
        }
#pragma unroll
        for (int i = 0; i < 2; i++) {
            int idx = tid + i * 256; int r = idx >> 4, q = idx & 15;
            *(float4*)&Ws[r][q * 4] = wbuf[i];
        }
        __syncthreads();

        int ktn = kt + 32;
        if (ktn < F_IN) {
#pragma unroll
            for (int i = 0; i < 4; i++) {
                int idx = tid + i * 256; int r = idx >> 3, q = idx & 7;
                int gr = row0 + r;
                xbuf[i] = (gr < N_NODES) ? *(const float4*)&x[(size_t)gr * F_IN + ktn + q * 4]
                                         : make_float4(0.f, 0.f, 0.f, 0.f);
            }
#pragma unroll
            for (int i = 0; i < 2; i++) {
                int idx = tid + i * 256; int r = idx >> 4, q = idx & 15;
                wbuf[i] = *(const float4*)&W1[(size_t)(ktn + r) * C1 + q * 4];
            }
        }

#pragma unroll
        for (int k = 0; k < 32; k++) {
            float4 b0 = *(const float4*)&Ws[k][tx * 8];
            float4 b1 = *(const float4*)&Ws[k][tx * 8 + 4];
#pragma unroll
            for (int i = 0; i < 4; i++) {
                float a = Xs[ty * 4 + i][k];
                acc[i][0] += a * b0.x; acc[i][1] += a * b0.y;
                acc[i][2] += a * b0.z; acc[i][3] += a * b0.w;
                acc[i][4] += a * b1.x; acc[i][5] += a * b1.y;
                acc[i][6] += a * b1.z; acc[i][7] += a * b1.w;
            }
        }
        __syncthreads();
    }

    // epilogue: thread's 8 cols are exactly head `tx` -> direct attention dots
    float asv[8], adv[8];
#pragma unroll
    for (int j = 0; j < 8; j++) { asv[j] = a_s[tx * 8 + j]; adv[j] = a_d[tx * 8 + j]; }

#pragma unroll
    for (int i = 0; i < 4; i++) {
        int r = row0 + ty * 4 + i;
        if (r < N_NODES) {
            float ps = 0.f, pd = 0.f;
#pragma unroll
            for (int j = 0; j < 8; j++) { ps += acc[i][j] * asv[j]; pd += acc[i][j] * adv[j]; }
            float* hp = &g_h1[(size_t)r * C1 + tx * 8];
            *(float4*)hp       = make_float4(acc[i][0], acc[i][1], acc[i][2], acc[i][3]);
            *(float4*)(hp + 4) = make_float4(acc[i][4], acc[i][5], acc[i][6], acc[i][7]);
            g_as1[r * H1 + tx] = ps;
            g_ad1[r * H1 + tx] = pd;
        }
    }
}

// ---------------- Aggregation layer 1 (warp per dst; no max-shift; 2 edges/iter) ----------------
__global__ void __launch_bounds__(256) agg1_kernel(const float* __restrict__ bias1) {
    int gw = (blockIdx.x * blockDim.x + threadIdx.x) >> 5;
    int lane = threadIdx.x & 31;
    if (gw >= N_NODES) return;
    int n = gw;
    int start = g_off[n], end = g_off[n + 1];

    // lanes 0-15 each own a head (lane&7) for one of two edge slots
    float adv = (lane < 16) ? g_ad1[n * H1 + (lane & 7)] : 0.f;
    int hA = lane >> 3;        // head of feature `lane`      (0..3)
    int hB = hA + 4;           // head of feature `lane+32`   (4..7)

    float accA = 0.f, accB = 0.f, denom = 0.f;
    int e = start;
    int s0 = (e     < end) ? g_csr[e]     : 0;
    int s1 = (e + 1 < end) ? g_csr[e + 1] : 0;

    while (e + 1 < end) {
        int p0n = (e + 2 < end) ? g_csr[e + 2] : 0;
        int p1n = (e + 3 < end) ? g_csr[e + 3] : 0;
        float w = 0.f;
        if (lane < 16) {
            int ss = (lane < 8) ? s0 : s1;
            float v = g_as1[ss * H1 + (lane & 7)] + adv;
            v = v > 0.f ? v : 0.2f * v;
            w = __expf(v);
            denom += w;
        }
        float wA0 = __shfl_sync(0xffffffffu, w, hA);
        float wB0 = __shfl_sync(0xffffffffu, w, hB);
        float wA1 = __shfl_sync(0xffffffffu, w, 8 + hA);
        float wB1 = __shfl_sync(0xffffffffu, w, 8 + hB);
        const float* p0 = &g_h1[(size_t)s0 * C1];
        const float* p1 = &g_h1[(size_t)s1 * C1];
        accA += wA0 * p0[lane];      accB += wB0 * p0[lane + 32];
        accA += wA1 * p1[lane];      accB += wB1 * p1[lane + 32];
        s0 = p0n; s1 = p1n; e += 2;
    }
    if (e < end) {  // odd tail (index already in s0)
        float w = 0.f;
        if (lane < 8) {
            float v = g_as1[s0 * H1 + lane] + adv;
            v = v > 0.f ? v : 0.2f * v;
            w = __expf(v);
            denom += w;
        }
        float wA = __shfl_sync(0xffffffffu, w, hA);
        float wB = __shfl_sync(0xffffffffu, w, hB);
        const float* p0 = &g_h1[(size_t)s0 * C1];
        accA += wA * p0[lane];  accB += wB * p0[lane + 32];
    }

    // head totals: lane h (even+tail) + lane h+8 (odd)
    float dh = denom + __shfl_xor_sync(0xffffffffu, denom, 8);
    float dA = __shfl_sync(0xffffffffu, dh, hA) + 1e-16f;
    float dB = __shfl_sync(0xffffffffu, dh, hB) + 1e-16f;
    float oA = accA / dA + bias1[lane];
    float oB = accB / dB + bias1[lane + 32];
    oA = oA > 0.f ? oA : expm1f(oA);
    oB = oB > 0.f ? oB : expm1f(oB);
    g_x2[(size_t)n * C1 + lane]      = oA;
    g_x2[(size_t)n * C1 + 32 + lane] = oB;
}

// ---------------- GEMM2: thread-per-node, 40 accumulators ----------------
__global__ void __launch_bounds__(128) gemm2_kernel(
        const float* __restrict__ W2,
        const float* __restrict__ a_s2, const float* __restrict__ a_d2) {
    __shared__ float Ws[C1][C2];     // 64x40, row-contiguous, 16B-aligned rows
    __shared__ float Xs[128][65];    // stride 65 -> conflict-free per-lane rows
    int tid = threadIdx.x;
    int n0 = blockIdx.x * 128;
    int gn = n0 + tid;

    for (int i = tid; i < C1 * C2; i += 128) ((float*)Ws)[i] = W2[i];
#pragma unroll
    for (int i = 0; i < 16; i++) {
        int idx = tid + i * 128; int r = idx >> 4, q = idx & 15;
        int gr = n0 + r;
        float4 v = (gr < N_NODES) ? *(const float4*)&g_x2[(size_t)gr * C1 + q * 4]
                                  : make_float4(0.f, 0.f, 0.f, 0.f);
        Xs[r][q * 4 + 0] = v.x; Xs[r][q * 4 + 1] = v.y;
        Xs[r][q * 4 + 2] = v.z; Xs[r][q * 4 + 3] = v.w;
    }
    __syncthreads();

    float acc[C2];
#pragma unroll
    for (int j = 0; j < C2; j++) acc[j] = 0.f;

    if (gn < N_NODES) {
#pragma unroll 4
        for (int k = 0; k < C1; k++) {
            float a = Xs[tid][k];
            const float4* wr = (const float4*)&Ws[k][0];   // broadcast across warp
#pragma unroll
            for (int j = 0; j < 10; j++) {
                float4 w4 = wr[j];
                acc[4*j+0] += a * w4.x; acc[4*j+1] += a * w4.y;
                acc[4*j+2] += a * w4.z; acc[4*j+3] += a * w4.w;
            }
        }
        float ps = 0.f, pd = 0.f;
        float* op = &g_h2[(size_t)gn * C2];
#pragma unroll
        for (int j = 0; j < 10; j++) {
            *(float4*)(op + 4*j) = make_float4(acc[4*j], acc[4*j+1], acc[4*j+2], acc[4*j+3]);
        }
#pragma unroll
        for (int c = 0; c < C2; c++) { ps += acc[c] * a_s2[c]; pd += acc[c] * a_d2[c]; }
        g_as2[gn] = ps;
        g_ad2[gn] = pd;
    }
}

// ---------------- Aggregation layer 2 + log_softmax (no max-shift; 2 edges/iter) ----------------
__global__ void __launch_bounds__(256) agg2_kernel(const float* __restrict__ bias2,
                                                   float* __restrict__ out) {
    int gw = (blockIdx.x * blockDim.x + threadIdx.x) >> 5;
    int lane = threadIdx.x & 31;
    if (gw >= N_NODES) return;
    int n = gw;
    int start = g_off[n], end = g_off[n + 1];
    float adv = g_ad2[n];

    float acc0 = 0.f, acc1 = 0.f, denom = 0.f;
    int e = start;
    int s0 = (e     < end) ? g_csr[e]     : 0;
    int s1 = (e + 1 < end) ? g_csr[e + 1] : 0;

    while (e + 1 < end) {
        int p0n = (e + 2 < end) ? g_csr[e + 2] : 0;
        int p1n = (e + 3 < end) ? g_csr[e + 3] : 0;
        float w = 0.f;
        if (lane < 2) {
            int ss = lane ? s1 : s0;
            float v = g_as2[ss] + adv;
            v = v > 0.f ? v : 0.2f * v;
            w = __expf(v);
            denom += w;
        }
        float w0 = __shfl_sync(0xffffffffu, w, 0);
        float w1 = __shfl_sync(0xffffffffu, w, 1);
        const float* p0 = &g_h2[(size_t)s0 * C2];
        const float* p1 = &g_h2[(size_t)s1 * C2];
        acc0 += w0 * p0[lane] + w1 * p1[lane];
        if (lane < 8) acc1 += w0 * p0[32 + lane] + w1 * p1[32 + lane];
        s0 = p0n; s1 = p1n; e += 2;
    }
    if (e < end) {
        float w = 0.f;
        if (lane == 0) {
            float v = g_as2[s0] + adv;
            v = v > 0.f ? v : 0.2f * v;
            w = __expf(v);
            denom += w;
        }
        float w0 = __shfl_sync(0xffffffffu, w, 0);
        const float* p0 = &g_h2[(size_t)s0 * C2];
        acc0 += w0 * p0[lane];
        if (lane < 8) acc1 += w0 * p0[32 + lane];
    }

    float d = __shfl_sync(0xffffffffu, denom, 0) + __shfl_sync(0xffffffffu, denom, 1) + 1e-16f;
    float r0 = acc0 / d + bias2[lane];
    float r1 = (lane < 8) ? (acc1 / d + bias2[32 + lane]) : -INFINITY;

    float mm = fmaxf(r0, r1);
#pragma unroll
    for (int o = 16; o > 0; o >>= 1)
        mm = fmaxf(mm, __shfl_xor_sync(0xffffffffu, mm, o));
    float ss = __expf(r0 - mm) + ((lane < 8) ? __expf(r1 - mm) : 0.f);
#pragma unroll
    for (int o = 16; o > 0; o >>= 1)
        ss += __shfl_xor_sync(0xffffffffu, ss, o);
    float lse = __logf(ss);

    out[(size_t)n * C2 + lane] = r0 - mm - lse;
    if (lane < 8) out[(size_t)n * C2 + 32 + lane] = r1 - mm - lse;
}

// ---------------- launch ----------------
extern "C" void kernel_launch(void* const* d_in, const int* in_sizes, int n_in,
                              void* d_out, int out_size) {
    const float* x     = (const float*)d_in[0];
    const int*   ei    = (const int*)  d_in[1];
    const float* W1    = (const float*)d_in[2];
    const float* as1   = (const float*)d_in[3];
    const float* ad1   = (const float*)d_in[4];
    const float* b1    = (const float*)d_in[5];
    const float* W2    = (const float*)d_in[6];
    const float* as2   = (const float*)d_in[7];
    const float* ad2   = (const float*)d_in[8];
    const float* b2    = (const float*)d_in[9];
    float* out = (float*)d_out;

    (void)in_sizes; (void)n_in; (void)out_size;

    zero_kernel   <<<(N_NODES + 255) / 256, 256>>>();
    hist_kernel   <<<(E_TOT + 255) / 256, 256>>>(ei);
    scan_kernel   <<<1, 1024>>>();
    scatter_kernel<<<(E_TOT + 255) / 256, 256>>>(ei);

    gemm1_kernel  <<<(N_NODES + 127) / 128, 256>>>(x, W1, as1, ad1);
    agg1_kernel   <<<(N_NODES * 32 + 255) / 256, 256>>>(b1);
    gemm2_kernel  <<<(N_NODES + 127) / 128, 128>>>(W2, as2, ad2);
    agg2_kernel   <<<(N_NODES * 32 + 255) / 256, 256>>>(b2, out);
}

// round 6
// speedup vs baseline: 1.1108x; 1.0815x over previous
#include <cuda_runtime.h>
#include <cuda_fp16.h>
#include <math.h>

#define N_NODES 100000
#define E_IN    1600000
#define E_TOT   (E_IN + N_NODES)
#define F_IN    256
#define H1      8
#define C1      64      /* H1*F1 */
#define C2      40      /* classes */

#define G1_BLOCKS ((N_NODES + 127) / 128)          /* 782 gemm1 tiles   */
#define HB_BLOCKS ((E_TOT + 255) / 256)            /* 6641 hist chunks  */

// ---------------- scratch (static device globals; no allocation) ----------------
__device__ uint4 g_h1p[(size_t)N_NODES * 8];   // layer-1 features, fp16: 8 halves per uint4, 8 uint4/row
__device__ float g_as1[(size_t)N_NODES * H1];
__device__ float g_ad1[(size_t)N_NODES * H1];
__device__ float g_x2 [(size_t)N_NODES * C1];
__device__ float g_h2 [(size_t)N_NODES * C2];
__device__ float g_as2[N_NODES];
__device__ float g_ad2[N_NODES];
__device__ int   g_deg[N_NODES];
__device__ int   g_cur[N_NODES];
__device__ int   g_off[N_NODES + 1];
__device__ int   g_csr[E_TOT];

// ---------------- f32x2 packed-math helpers (PTX ISA 8.7, sm_100+) ----------------
__device__ __forceinline__ unsigned long long packf2(float a, float b) {
    unsigned long long r;
    asm("mov.b64 %0, {%1, %2};" : "=l"(r) : "f"(a), "f"(b));
    return r;
}
__device__ __forceinline__ void fma2(unsigned long long& d,
                                     unsigned long long a, unsigned long long b) {
    asm("fma.rn.f32x2 %0, %1, %2, %0;" : "+l"(d) : "l"(a), "l"(b));
}
__device__ __forceinline__ float2 unpk(unsigned long long v) {
    float2 r;
    asm("mov.b64 {%0, %1}, %2;" : "=f"(r.x), "=f"(r.y) : "l"(v));
    return r;
}

// ---------------- CSR build ----------------
__global__ void zero_kernel() {
    int i = blockIdx.x * blockDim.x + threadIdx.x;
    if (i < N_NODES) { g_deg[i] = 0; g_cur[i] = 0; }
}

__global__ void scan_kernel() {
    __shared__ int sums[1024];
    int t = threadIdx.x;
    const int SEG = (N_NODES + 1023) / 1024;
    int b = t * SEG;
    int e = b + SEG; if (e > N_NODES) e = N_NODES;
    int s = 0;
    for (int i = b; i < e; i++) s += g_deg[i];
    sums[t] = s;
    __syncthreads();
    for (int o = 1; o < 1024; o <<= 1) {
        int v = (t >= o) ? sums[t - o] : 0;
        __syncthreads();
        if (t >= o) sums[t] += v;
        __syncthreads();
    }
    int run = (t == 0) ? 0 : sums[t - 1];
    for (int i = b; i < e; i++) { g_off[i] = run; run += g_deg[i]; }
    if (t == 0) g_off[N_NODES] = E_TOT;
}

__global__ void scatter_kernel(const int* __restrict__ ei) {
    int i = blockIdx.x * blockDim.x + threadIdx.x;
    if (i >= E_TOT) return;
    int d, s;
    if (i < E_IN) { s = ei[i]; d = ei[E_IN + i]; }
    else          { s = i - E_IN; d = i - E_IN; }
    int p = g_off[d] + atomicAdd(&g_cur[d], 1);
    g_csr[p] = s;
}

// ---------------- fat kernel: gemm1 tiles (blocks < G1_BLOCKS) || hist (rest) ----------------
// gemm1: 256 threads, 128x64 tile, K-tile 32, 4x8 micro-tile, f32x2 FMAs.
// tx = col group of 8 (== head index), ty = row group of 4.
__global__ void __launch_bounds__(256) fat1_kernel(
        const float* __restrict__ x, const float* __restrict__ W1,
        const float* __restrict__ a_s, const float* __restrict__ a_d,
        const int* __restrict__ ei) {
    __shared__ float Xs[128][33];
    __shared__ float Ws[32][64];
    int tid = threadIdx.x;

    if (blockIdx.x >= G1_BLOCKS) {
        // ---- hist path ----
        int i = (blockIdx.x - G1_BLOCKS) * 256 + tid;
        if (i < E_TOT) {
            int d = (i < E_IN) ? ei[E_IN + i] : (i - E_IN);
            atomicAdd(&g_deg[d], 1);
        }
        return;
    }

    // ---- gemm1 path ----
    int tx = tid & 7;
    int ty = tid >> 3;
    int row0 = blockIdx.x * 128;

    unsigned long long acc2[4][4];
#pragma unroll
    for (int i = 0; i < 4; i++)
#pragma unroll
        for (int j = 0; j < 4; j++) acc2[i][j] = 0ull;

    float4 xbuf[4];
    float4 wbuf[2];
#pragma unroll
    for (int i = 0; i < 4; i++) {
        int idx = tid + i * 256; int r = idx >> 3, q = idx & 7;
        int gr = row0 + r;
        xbuf[i] = (gr < N_NODES) ? *(const float4*)&x[(size_t)gr * F_IN + q * 4]
                                 : make_float4(0.f, 0.f, 0.f, 0.f);
    }
#pragma unroll
    for (int i = 0; i < 2; i++) {
        int idx = tid + i * 256; int r = idx >> 4, q = idx & 15;
        wbuf[i] = *(const float4*)&W1[(size_t)r * C1 + q * 4];
    }

    for (int kt = 0; kt < F_IN; kt += 32) {
#pragma unroll
        for (int i = 0; i < 4; i++) {
            int idx = tid + i * 256; int r = idx >> 3, q = idx & 7;
            Xs[r][q * 4 + 0] = xbuf[i].x; Xs[r][q * 4 + 1] = xbuf[i].y;
            Xs[r][q * 4 + 2] = xbuf[i].z; Xs[r][q * 4 + 3] = xbuf[i].w;
        }
#pragma unroll
        for (int i = 0; i < 2; i++) {
            int idx = tid + i * 256; int r = idx >> 4, q = idx & 15;
            *(float4*)&Ws[r][q * 4] = wbuf[i];
        }
        __syncthreads();

        int ktn = kt + 32;
        if (ktn < F_IN) {
#pragma unroll
            for (int i = 0; i < 4; i++) {
                int idx = tid + i * 256; int r = idx >> 3, q = idx & 7;
                int gr = row0 + r;
                xbuf[i] = (gr < N_NODES) ? *(const float4*)&x[(size_t)gr * F_IN + ktn + q * 4]
                                         : make_float4(0.f, 0.f, 0.f, 0.f);
            }
#pragma unroll
            for (int i = 0; i < 2; i++) {
                int idx = tid + i * 256; int r = idx >> 4, q = idx & 15;
                wbuf[i] = *(const float4*)&W1[(size_t)(ktn + r) * C1 + q * 4];
            }
        }

#pragma unroll
        for (int k = 0; k < 32; k++) {
            const unsigned long long* wp = (const unsigned long long*)&Ws[k][tx * 8];
            unsigned long long b0 = wp[0], b1 = wp[1], b2 = wp[2], b3 = wp[3];
#pragma unroll
            for (int i = 0; i < 4; i++) {
                float a = Xs[ty * 4 + i][k];
                unsigned long long ap = packf2(a, a);
                fma2(acc2[i][0], ap, b0);
                fma2(acc2[i][1], ap, b1);
                fma2(acc2[i][2], ap, b2);
                fma2(acc2[i][3], ap, b3);
            }
        }
        __syncthreads();
    }

    // epilogue: thread's 8 cols are exactly head `tx`
    float asv[8], adv[8];
#pragma unroll
    for (int j = 0; j < 8; j++) { asv[j] = a_s[tx * 8 + j]; adv[j] = a_d[tx * 8 + j]; }

#pragma unroll
    for (int i = 0; i < 4; i++) {
        int r = row0 + ty * 4 + i;
        if (r < N_NODES) {
            float f[8];
#pragma unroll
            for (int j = 0; j < 4; j++) {
                float2 p = unpk(acc2[i][j]);
                f[2 * j] = p.x; f[2 * j + 1] = p.y;
            }
            float ps = 0.f, pd = 0.f;
#pragma unroll
            for (int j = 0; j < 8; j++) { ps += f[j] * asv[j]; pd += f[j] * adv[j]; }
            // pack 8 floats -> 8 halves -> one 16B store
            __half2 hh[4];
#pragma unroll
            for (int j = 0; j < 4; j++) hh[j] = __floats2half2_rn(f[2 * j], f[2 * j + 1]);
            g_h1p[(size_t)r * 8 + tx] = *(uint4*)hh;
            g_as1[r * H1 + tx] = ps;
            g_ad1[r * H1 + tx] = pd;
        }
    }
}

// ---------------- Aggregation layer 1 (warp per dst; fp16 gather; 2 edges/iter) ----------------
// Lane owns features (2*lane, 2*lane+1) = half2 #lane of the row; head = lane>>2.
__global__ void __launch_bounds__(256) agg1_kernel(const float* __restrict__ bias1) {
    int gw = (blockIdx.x * blockDim.x + threadIdx.x) >> 5;
    int lane = threadIdx.x & 31;
    if (gw >= N_NODES) return;
    int n = gw;
    int start = g_off[n], end = g_off[n + 1];

    float adv = (lane < 16) ? g_ad1[n * H1 + (lane & 7)] : 0.f;
    int hA = lane >> 2;            // head of this lane's feature pair

    float accLo = 0.f, accHi = 0.f, denom = 0.f;
    int e = start;
    int s0 = (e     < end) ? g_csr[e]     : 0;
    int s1 = (e + 1 < end) ? g_csr[e + 1] : 0;

    while (e + 1 < end) {
        int p0n = (e + 2 < end) ? g_csr[e + 2] : 0;
        int p1n = (e + 3 < end) ? g_csr[e + 3] : 0;
        float w = 0.f;
        if (lane < 16) {
            int ss = (lane < 8) ? s0 : s1;
            float v = g_as1[ss * H1 + (lane & 7)] + adv;
            v = v > 0.f ? v : 0.2f * v;
            w = __expf(v);
            denom += w;
        }
        float w0 = __shfl_sync(0xffffffffu, w, hA);
        float w1 = __shfl_sync(0xffffffffu, w, 8 + hA);
        __half2 h0 = ((const __half2*)&g_h1p[(size_t)s0 * 8])[lane];
        __half2 h1 = ((const __half2*)&g_h1p[(size_t)s1 * 8])[lane];
        float2 f0 = __half22float2(h0);
        float2 f1 = __half22float2(h1);
        accLo += w0 * f0.x + w1 * f1.x;
        accHi += w0 * f0.y + w1 * f1.y;
        s0 = p0n; s1 = p1n; e += 2;
    }
    if (e < end) {  // odd tail
        float w = 0.f;
        if (lane < 8) {
            float v = g_as1[s0 * H1 + lane] + adv;
            v = v > 0.f ? v : 0.2f * v;
            w = __expf(v);
            denom += w;
        }
        float w0 = __shfl_sync(0xffffffffu, w, hA);
        __half2 h0 = ((const __half2*)&g_h1p[(size_t)s0 * 8])[lane];
        float2 f0 = __half22float2(h0);
        accLo += w0 * f0.x;
        accHi += w0 * f0.y;
    }

    float dh = denom + __shfl_xor_sync(0xffffffffu, denom, 8);   // per-head total in lanes 0-7
    float dA = __shfl_sync(0xffffffffu, dh, hA) + 1e-16f;
    float oLo = accLo / dA + bias1[2 * lane];
    float oHi = accHi / dA + bias1[2 * lane + 1];
    oLo = oLo > 0.f ? oLo : expm1f(oLo);
    oHi = oHi > 0.f ? oHi : expm1f(oHi);
    *(float2*)&g_x2[(size_t)n * C1 + 2 * lane] = make_float2(oLo, oHi);
}

// ---------------- GEMM2: thread-per-node, 20 f32x2 accumulators ----------------
__global__ void __launch_bounds__(128) gemm2_kernel(
        const float* __restrict__ W2,
        const float* __restrict__ a_s2, const float* __restrict__ a_d2) {
    __shared__ float Ws[C1][C2];     // 64x40
    __shared__ float Xs[128][65];
    int tid = threadIdx.x;
    int n0 = blockIdx.x * 128;
    int gn = n0 + tid;

    for (int i = tid; i < C1 * C2; i += 128) ((float*)Ws)[i] = W2[i];
#pragma unroll
    for (int i = 0; i < 16; i++) {
        int idx = tid + i * 128; int r = idx >> 4, q = idx & 15;
        int gr = n0 + r;
        float4 v = (gr < N_NODES) ? *(const float4*)&g_x2[(size_t)gr * C1 + q * 4]
                                  : make_float4(0.f, 0.f, 0.f, 0.f);
        Xs[r][q * 4 + 0] = v.x; Xs[r][q * 4 + 1] = v.y;
        Xs[r][q * 4 + 2] = v.z; Xs[r][q * 4 + 3] = v.w;
    }
    __syncthreads();

    unsigned long long acc2[20];
#pragma unroll
    for (int j = 0; j < 20; j++) acc2[j] = 0ull;

    if (gn < N_NODES) {
#pragma unroll 4
        for (int k = 0; k < C1; k++) {
            float a = Xs[tid][k];
            unsigned long long ap = packf2(a, a);
            const unsigned long long* wp = (const unsigned long long*)&Ws[k][0];
#pragma unroll
            for (int j = 0; j < 20; j++) fma2(acc2[j], ap, wp[j]);
        }
        float ps = 0.f, pd = 0.f;
        float* op = &g_h2[(size_t)gn * C2];
#pragma unroll
        for (int j = 0; j < 20; j++) {
            *(unsigned long long*)(op + 2 * j) = acc2[j];     // 8B store of the pair
            float2 p = unpk(acc2[j]);
            ps += p.x * a_s2[2 * j] + p.y * a_s2[2 * j + 1];
            pd += p.x * a_d2[2 * j] + p.y * a_d2[2 * j + 1];
        }
        g_as2[gn] = ps;
        g_ad2[gn] = pd;
    }
}

// ---------------- Aggregation layer 2 + log_softmax (4 edges/iter) ----------------
__global__ void __launch_bounds__(256) agg2_kernel(const float* __restrict__ bias2,
                                                   float* __restrict__ out) {
    int gw = (blockIdx.x * blockDim.x + threadIdx.x) >> 5;
    int lane = threadIdx.x & 31;
    if (gw >= N_NODES) return;
    int n = gw;
    int start = g_off[n], end = g_off[n + 1];
    float adv = g_ad2[n];

    float acc0 = 0.f, acc1 = 0.f, denom = 0.f;
    int e = start;
    int s[4];
#pragma unroll
    for (int j = 0; j < 4; j++) s[j] = (e + j < end) ? g_csr[e + j] : 0;

    while (e + 3 < end) {
        int ns[4];
#pragma unroll
        for (int j = 0; j < 4; j++) ns[j] = (e + 4 + j < end) ? g_csr[e + 4 + j] : 0;
        float w = 0.f;
        if (lane < 4) {
            float v = g_as2[s[lane]] + adv;
            v = v > 0.f ? v : 0.2f * v;
            w = __expf(v);
            denom += w;
        }
#pragma unroll
        for (int j = 0; j < 4; j++) {
            float wj = __shfl_sync(0xffffffffu, w, j);
            const float* p = &g_h2[(size_t)s[j] * C2];
            acc0 += wj * p[lane];
            if (lane < 8) acc1 += wj * p[32 + lane];
        }
#pragma unroll
        for (int j = 0; j < 4; j++) s[j] = ns[j];
        e += 4;
    }
    // tail: 0-3 edges (indices already staged in s[0..3])
    for (int j = 0; e < end; e++, j++) {
        int sv = s[j];
        float w = 0.f;
        if (lane == 0) {
            float v = g_as2[sv] + adv;
            v = v > 0.f ? v : 0.2f * v;
            w = __expf(v);
            denom += w;
        }
        float wj = __shfl_sync(0xffffffffu, w, 0);
        const float* p = &g_h2[(size_t)sv * C2];
        acc0 += wj * p[lane];
        if (lane < 8) acc1 += wj * p[32 + lane];
    }

    denom += __shfl_xor_sync(0xffffffffu, denom, 1);
    denom += __shfl_xor_sync(0xffffffffu, denom, 2);
    float d = __shfl_sync(0xffffffffu, denom, 0) + 1e-16f;
    float r0 = acc0 / d + bias2[lane];
    float r1 = (lane < 8) ? (acc1 / d + bias2[32 + lane]) : -INFINITY;

    float mm = fmaxf(r0, r1);
#pragma unroll
    for (int o = 16; o > 0; o >>= 1)
        mm = fmaxf(mm, __shfl_xor_sync(0xffffffffu, mm, o));
    float ss = __expf(r0 - mm) + ((lane < 8) ? __expf(r1 - mm) : 0.f);
#pragma unroll
    for (int o = 16; o > 0; o >>= 1)
        ss += __shfl_xor_sync(0xffffffffu, ss, o);
    float lse = __logf(ss);

    out[(size_t)n * C2 + lane] = r0 - mm - lse;
    if (lane < 8) out[(size_t)n * C2 + 32 + lane] = r1 - mm - lse;
}

// ---------------- launch ----------------
extern "C" void kernel_launch(void* const* d_in, const int* in_sizes, int n_in,
                              void* d_out, int out_size) {
    const float* x     = (const float*)d_in[0];
    const int*   ei    = (const int*)  d_in[1];
    const float* W1    = (const float*)d_in[2];
    const float* as1   = (const float*)d_in[3];
    const float* ad1   = (const float*)d_in[4];
    const float* b1    = (const float*)d_in[5];
    const float* W2    = (const float*)d_in[6];
    const float* as2   = (const float*)d_in[7];
    const float* ad2   = (const float*)d_in[8];
    const float* b2    = (const float*)d_in[9];
    float* out = (float*)d_out;

    (void)in_sizes; (void)n_in; (void)out_size;

    zero_kernel   <<<(N_NODES + 255) / 256, 256>>>();
    fat1_kernel   <<<G1_BLOCKS + HB_BLOCKS, 256>>>(x, W1, as1, ad1, ei);  // gemm1 || hist
    scan_kernel   <<<1, 1024>>>();
    scatter_kernel<<<HB_BLOCKS, 256>>>(ei);

    agg1_kernel   <<<(N_NODES * 32 + 255) / 256, 256>>>(b1);
    gemm2_kernel  <<<(N_NODES + 127) / 128, 128>>>(W2, as2, ad2);
    agg2_kernel   <<<(N_NODES * 32 + 255) / 256, 256>>>(b2, out);
}

// round 10
// speedup vs baseline: 1.6690x; 1.5026x over previous
#include <cuda_runtime.h>
#include <cuda_fp16.h>
#include <math.h>

#define N_NODES 100000
#define E_IN    1600000
#define E_TOT   (E_IN + N_NODES)
#define F_IN    256
#define H1      8
#define C1      64      /* H1*F1 */
#define C2      40      /* classes */

#define G1_BLOCKS ((N_NODES + 127) / 128)          /* 782 gemm1 tiles   */
#define HB_BLOCKS ((E_TOT + 255) / 256)            /* 6641 hist chunks  */
#define SC_BLOCKS ((N_NODES + 255) / 256)          /* 391 scan blocks   */

// ---------------- scratch (static device globals; no allocation) ----------------
__device__ uint4 g_h1p[(size_t)N_NODES * 8];   // layer-1 features, fp16: 8 halves per uint4
__device__ float g_as1[(size_t)N_NODES * H1];
__device__ float g_ad1[(size_t)N_NODES * H1];
__device__ float g_x2 [(size_t)N_NODES * C1];
__device__ float g_h2 [(size_t)N_NODES * C2];
__device__ float g_as2[N_NODES];
__device__ float g_ad2[N_NODES];
__device__ int   g_deg[N_NODES];
__device__ int   g_cur[N_NODES];
__device__ int   g_off[N_NODES + 1];
__device__ int   g_csr[E_TOT];
__device__ int   g_part[SC_BLOCKS];
__device__ int   g_poff[SC_BLOCKS];

// ---------------- helpers ----------------
// cvt.rna.tf32.f32 destination is a .b32 register; result is a valid f32 bit pattern
__device__ __forceinline__ float tf32r(float v) {
    unsigned u;
    asm("cvt.rna.tf32.f32 %0, %1;" : "=r"(u) : "f"(v));
    return __uint_as_float(u);
}
// tf32 mma: A/B fragments are .b32 registers (bit patterns), C/D are .f32
__device__ __forceinline__ void mma_tf32(float* c, const unsigned* a, const unsigned* b) {
    asm volatile(
        "mma.sync.aligned.m16n8k8.row.col.f32.tf32.tf32.f32 "
        "{%0,%1,%2,%3}, {%4,%5,%6,%7}, {%8,%9}, {%0,%1,%2,%3};\n"
        : "+f"(c[0]), "+f"(c[1]), "+f"(c[2]), "+f"(c[3])
        : "r"(a[0]), "r"(a[1]), "r"(a[2]), "r"(a[3]), "r"(b[0]), "r"(b[1]));
}
__device__ __forceinline__ unsigned long long packf2(float a, float b) {
    unsigned long long r;
    asm("mov.b64 %0, {%1, %2};" : "=l"(r) : "f"(a), "f"(b));
    return r;
}
__device__ __forceinline__ void fma2(unsigned long long& d,
                                     unsigned long long a, unsigned long long b) {
    asm("fma.rn.f32x2 %0, %1, %2, %0;" : "+l"(d) : "l"(a), "l"(b));
}
__device__ __forceinline__ float2 unpk(unsigned long long v) {
    float2 r;
    asm("mov.b64 {%0, %1}, %2;" : "=f"(r.x), "=f"(r.y) : "l"(v));
    return r;
}

// ---------------- CSR build ----------------
__global__ void zero_kernel() {
    int i = blockIdx.x * blockDim.x + threadIdx.x;
    if (i < N_NODES) { g_deg[i] = 0; g_cur[i] = 0; }
}

// scan phase A: per-block sums of g_deg
__global__ void scanA_kernel() {
    __shared__ int ws[8];
    int tid = threadIdx.x;
    int i = blockIdx.x * 256 + tid;
    int v = (i < N_NODES) ? g_deg[i] : 0;
    int s = v;
#pragma unroll
    for (int o = 16; o > 0; o >>= 1) s += __shfl_xor_sync(0xffffffffu, s, o);
    if ((tid & 31) == 0) ws[tid >> 5] = s;
    __syncthreads();
    if (tid < 8) {
        int t = ws[tid];
#pragma unroll
        for (int o = 4; o > 0; o >>= 1) t += __shfl_xor_sync(0xffu, t, o);
        if (tid == 0) g_part[blockIdx.x] = t;
    }
}

// scan phase B: exclusive scan over SC_BLOCKS partials (1 block, 512 thr)
__global__ void scanB_kernel() {
    __shared__ int sh[512];
    int t = threadIdx.x;
    int v = (t < SC_BLOCKS) ? g_part[t] : 0;
    sh[t] = v;
    __syncthreads();
    for (int o = 1; o < 512; o <<= 1) {
        int u = (t >= o) ? sh[t - o] : 0;
        __syncthreads();
        sh[t] += u;
        __syncthreads();
    }
    if (t < SC_BLOCKS) g_poff[t] = sh[t] - v;    // exclusive
}

// scan phase C: block-local exclusive scan + global offset -> g_off
__global__ void scanC_kernel() {
    __shared__ int ws[8];
    int tid = threadIdx.x;
    int i = blockIdx.x * 256 + tid;
    int v = (i < N_NODES) ? g_deg[i] : 0;
    int inc = v;
#pragma unroll
    for (int o = 1; o < 32; o <<= 1) {
        int u = __shfl_up_sync(0xffffffffu, inc, o);
        if ((tid & 31) >= o) inc += u;
    }
    if ((tid & 31) == 31) ws[tid >> 5] = inc;
    __syncthreads();
    if (tid < 8) {
        int t = ws[tid];
#pragma unroll
        for (int o = 1; o < 8; o <<= 1) {
            int u = __shfl_up_sync(0xffu, t, o);
            if (tid >= o) t += u;
        }
        ws[tid] = t;
    }
    __syncthreads();
    int wbase = (tid >= 32) ? ws[(tid >> 5) - 1] : 0;
    int excl = g_poff[blockIdx.x] + wbase + inc - v;
    if (i < N_NODES) {
        g_off[i] = excl;
        if (i == N_NODES - 1) g_off[N_NODES] = excl + v;  // == E_TOT
    }
}

__global__ void scatter_kernel(const int* __restrict__ ei) {
    int i = blockIdx.x * blockDim.x + threadIdx.x;
    if (i >= E_TOT) return;
    int d, s;
    if (i < E_IN) { s = ei[i]; d = ei[E_IN + i]; }
    else          { s = i - E_IN; d = i - E_IN; }
    int p = g_off[d] + atomicAdd(&g_cur[d], 1);
    g_csr[p] = s;
}

// ---------------- fat kernel: gemm1 (tf32 mma.sync) || hist ----------------
// gemm1: 256 threads, 128x64 tile, K-tile 32. 8 warps in 4x2 grid of 32x32 warp tiles.
__global__ void __launch_bounds__(256) fat1_kernel(
        const float* __restrict__ x, const float* __restrict__ W1,
        const float* __restrict__ a_s, const float* __restrict__ a_d,
        const int* __restrict__ ei) {
    __shared__ __align__(16) float smem_pool[128 * 65];   // 33280B, aliased
    int tid = threadIdx.x;

    if (blockIdx.x >= G1_BLOCKS) {
        // ---- hist path ----
        int i = (blockIdx.x - G1_BLOCKS) * 256 + tid;
        if (i < E_TOT) {
            int d = (i < E_IN) ? ei[E_IN + i] : (i - E_IN);
            atomicAdd(&g_deg[d], 1);
        }
        return;
    }

    float (*Xs)[33] = (float (*)[33])smem_pool;                    // 128x33
    float (*Ws)[64] = (float (*)[64])(smem_pool + 128 * 33);       // 32x64
    float (*Cs)[65] = (float (*)[65])smem_pool;                    // reused after K-loop

    int lane = tid & 31;
    int warp = tid >> 5;
    int rg = warp >> 1;          // row group: rows rg*32 .. +31
    int cg = warp & 1;           // col group: cols cg*32 .. +31
    int row0 = blockIdx.x * 128;

    float acc[2][4][4];          // [m-tile][n-tile][reg]
#pragma unroll
    for (int m = 0; m < 2; m++)
#pragma unroll
        for (int j = 0; j < 4; j++)
#pragma unroll
            for (int q = 0; q < 4; q++) acc[m][j][q] = 0.f;

    float4 xbuf[4];
    float4 wbuf[2];
#pragma unroll
    for (int i = 0; i < 4; i++) {
        int idx = tid + i * 256; int r = idx >> 3, q = idx & 7;
        int gr = row0 + r;
        xbuf[i] = (gr < N_NODES) ? *(const float4*)&x[(size_t)gr * F_IN + q * 4]
                                 : make_float4(0.f, 0.f, 0.f, 0.f);
    }
#pragma unroll
    for (int i = 0; i < 2; i++) {
        int idx = tid + i * 256; int r = idx >> 4, q = idx & 15;
        wbuf[i] = *(const float4*)&W1[(size_t)r * C1 + q * 4];
    }

    for (int kt = 0; kt < F_IN; kt += 32) {
        // commit tiles (tf32-rounded)
#pragma unroll
        for (int i = 0; i < 4; i++) {
            int idx = tid + i * 256; int r = idx >> 3, q = idx & 7;
            Xs[r][q * 4 + 0] = tf32r(xbuf[i].x); Xs[r][q * 4 + 1] = tf32r(xbuf[i].y);
            Xs[r][q * 4 + 2] = tf32r(xbuf[i].z); Xs[r][q * 4 + 3] = tf32r(xbuf[i].w);
        }
#pragma unroll
        for (int i = 0; i < 2; i++) {
            int idx = tid + i * 256; int r = idx >> 4, q = idx & 15;
            Ws[r][q * 4 + 0] = tf32r(wbuf[i].x); Ws[r][q * 4 + 1] = tf32r(wbuf[i].y);
            Ws[r][q * 4 + 2] = tf32r(wbuf[i].z); Ws[r][q * 4 + 3] = tf32r(wbuf[i].w);
        }
        __syncthreads();

        int ktn = kt + 32;
        if (ktn < F_IN) {
#pragma unroll
            for (int i = 0; i < 4; i++) {
                int idx = tid + i * 256; int r = idx >> 3, q = idx & 7;
                int gr = row0 + r;
                xbuf[i] = (gr < N_NODES) ? *(const float4*)&x[(size_t)gr * F_IN + ktn + q * 4]
                                         : make_float4(0.f, 0.f, 0.f, 0.f);
            }
#pragma unroll
            for (int i = 0; i < 2; i++) {
                int idx = tid + i * 256; int r = idx >> 4, q = idx & 15;
                wbuf[i] = *(const float4*)&W1[(size_t)(ktn + r) * C1 + q * 4];
            }
        }

        // 4 k-steps of 8 within this K-tile
#pragma unroll
        for (int ks = 0; ks < 4; ks++) {
            int k0 = ks * 8;
            unsigned afr[2][4];
#pragma unroll
            for (int m = 0; m < 2; m++) {
                int R = rg * 32 + m * 16;
                afr[m][0] = __float_as_uint(Xs[R + (lane >> 2)][k0 + (lane & 3)]);
                afr[m][1] = __float_as_uint(Xs[R + (lane >> 2) + 8][k0 + (lane & 3)]);
                afr[m][2] = __float_as_uint(Xs[R + (lane >> 2)][k0 + (lane & 3) + 4]);
                afr[m][3] = __float_as_uint(Xs[R + (lane >> 2) + 8][k0 + (lane & 3) + 4]);
            }
            unsigned bfr[4][2];
#pragma unroll
            for (int j = 0; j < 4; j++) {
                int Cb = cg * 32 + j * 8;
                bfr[j][0] = __float_as_uint(Ws[k0 + (lane & 3)][Cb + (lane >> 2)]);
                bfr[j][1] = __float_as_uint(Ws[k0 + (lane & 3) + 4][Cb + (lane >> 2)]);
            }
#pragma unroll
            for (int m = 0; m < 2; m++)
#pragma unroll
                for (int j = 0; j < 4; j++)
                    mma_tf32(acc[m][j], afr[m], bfr[j]);
        }
        __syncthreads();
    }

    // stage accumulators to shared (Cs aliases Xs/Ws; sync above guarantees done)
#pragma unroll
    for (int m = 0; m < 2; m++) {
        int R = rg * 32 + m * 16 + (lane >> 2);
#pragma unroll
        for (int j = 0; j < 4; j++) {
            int Cb = cg * 32 + j * 8 + 2 * (lane & 3);
            Cs[R][Cb]         = acc[m][j][0];
            Cs[R][Cb + 1]     = acc[m][j][1];
            Cs[R + 8][Cb]     = acc[m][j][2];
            Cs[R + 8][Cb + 1] = acc[m][j][3];
        }
    }
    __syncthreads();

    // epilogue: thread handles half a row (32 cols = 4 heads)
    {
        int r = tid >> 1;
        int half = tid & 1;
        int gr = row0 + r;
        if (gr < N_NODES) {
            int c0 = half * 32;
            float f[32];
#pragma unroll
            for (int q = 0; q < 32; q++) f[q] = Cs[r][c0 + q];
#pragma unroll
            for (int h = 0; h < 4; h++) {
                int head = half * 4 + h;
                float ps = 0.f, pd = 0.f;
#pragma unroll
                for (int q = 0; q < 8; q++) {
                    ps += f[h * 8 + q] * a_s[head * 8 + q];
                    pd += f[h * 8 + q] * a_d[head * 8 + q];
                }
                g_as1[gr * H1 + head] = ps;
                g_ad1[gr * H1 + head] = pd;
            }
            // pack 32 floats -> 16 half2 -> 4 uint4
#pragma unroll
            for (int u = 0; u < 4; u++) {
                __half2 hh[4];
#pragma unroll
                for (int q = 0; q < 4; q++)
                    hh[q] = __floats2half2_rn(f[u * 8 + 2 * q], f[u * 8 + 2 * q + 1]);
                g_h1p[(size_t)gr * 8 + half * 4 + u] = *(uint4*)hh;
            }
        }
    }
}

// ---------------- Aggregation layer 1 (warp per dst; fp16 gather; 2 edges/iter) ----------------
__global__ void __launch_bounds__(256) agg1_kernel(const float* __restrict__ bias1) {
    int gw = (blockIdx.x * blockDim.x + threadIdx.x) >> 5;
    int lane = threadIdx.x & 31;
    if (gw >= N_NODES) return;
    int n = gw;
    int start = g_off[n], end = g_off[n + 1];

    float adv = (lane < 16) ? g_ad1[n * H1 + (lane & 7)] : 0.f;
    int hA = lane >> 2;            // head of this lane's feature pair

    float accLo = 0.f, accHi = 0.f, denom = 0.f;
    int e = start;
    int s0 = (e     < end) ? g_csr[e]     : 0;
    int s1 = (e + 1 < end) ? g_csr[e + 1] : 0;

    while (e + 1 < end) {
        int p0n = (e + 2 < end) ? g_csr[e + 2] : 0;
        int p1n = (e + 3 < end) ? g_csr[e + 3] : 0;
        float w = 0.f;
        if (lane < 16) {
            int ss = (lane < 8) ? s0 : s1;
            float v = g_as1[ss * H1 + (lane & 7)] + adv;
            v = v > 0.f ? v : 0.2f * v;
            w = __expf(v);
            denom += w;
        }
        float w0 = __shfl_sync(0xffffffffu, w, hA);
        float w1 = __shfl_sync(0xffffffffu, w, 8 + hA);
        __half2 h0 = ((const __half2*)&g_h1p[(size_t)s0 * 8])[lane];
        __half2 h1 = ((const __half2*)&g_h1p[(size_t)s1 * 8])[lane];
        float2 f0 = __half22float2(h0);
        float2 f1 = __half22float2(h1);
        accLo += w0 * f0.x + w1 * f1.x;
        accHi += w0 * f0.y + w1 * f1.y;
        s0 = p0n; s1 = p1n; e += 2;
    }
    if (e < end) {  // odd tail
        float w = 0.f;
        if (lane < 8) {
            float v = g_as1[s0 * H1 + lane] + adv;
            v = v > 0.f ? v : 0.2f * v;
            w = __expf(v);
            denom += w;
        }
        float w0 = __shfl_sync(0xffffffffu, w, hA);
        __half2 h0 = ((const __half2*)&g_h1p[(size_t)s0 * 8])[lane];
        float2 f0 = __half22float2(h0);
        accLo += w0 * f0.x;
        accHi += w0 * f0.y;
    }

    float dh = denom + __shfl_xor_sync(0xffffffffu, denom, 8);
    float dA = __shfl_sync(0xffffffffu, dh, hA) + 1e-16f;
    float oLo = accLo / dA + bias1[2 * lane];
    float oHi = accHi / dA + bias1[2 * lane + 1];
    oLo = oLo > 0.f ? oLo : expm1f(oLo);
    oHi = oHi > 0.f ? oHi : expm1f(oHi);
    *(float2*)&g_x2[(size_t)n * C1 + 2 * lane] = make_float2(oLo, oHi);
}

// ---------------- GEMM2: thread-per-node, 20 f32x2 accumulators ----------------
__global__ void __launch_bounds__(128) gemm2_kernel(
        const float* __restrict__ W2,
        const float* __restrict__ a_s2, const float* __restrict__ a_d2) {
    __shared__ float Ws[C1][C2];
    __shared__ float Xs[128][65];
    int tid = threadIdx.x;
    int n0 = blockIdx.x * 128;
    int gn = n0 + tid;

    for (int i = tid; i < C1 * C2; i += 128) ((float*)Ws)[i] = W2[i];
#pragma unroll
    for (int i = 0; i < 16; i++) {
        int idx = tid + i * 128; int r = idx >> 4, q = idx & 15;
        int gr = n0 + r;
        float4 v = (gr < N_NODES) ? *(const float4*)&g_x2[(size_t)gr * C1 + q * 4]
                                  : make_float4(0.f, 0.f, 0.f, 0.f);
        Xs[r][q * 4 + 0] = v.x; Xs[r][q * 4 + 1] = v.y;
        Xs[r][q * 4 + 2] = v.z; Xs[r][q * 4 + 3] = v.w;
    }
    __syncthreads();

    unsigned long long acc2[20];
#pragma unroll
    for (int j = 0; j < 20; j++) acc2[j] = 0ull;

    if (gn < N_NODES) {
#pragma unroll 4
        for (int k = 0; k < C1; k++) {
            float a = Xs[tid][k];
            unsigned long long ap = packf2(a, a);
            const unsigned long long* wp = (const unsigned long long*)&Ws[k][0];
#pragma unroll
            for (int j = 0; j < 20; j++) fma2(acc2[j], ap, wp[j]);
        }
        float ps = 0.f, pd = 0.f;
        float* op = &g_h2[(size_t)gn * C2];
#pragma unroll
        for (int j = 0; j < 20; j++) {
            *(unsigned long long*)(op + 2 * j) = acc2[j];
            float2 p = unpk(acc2[j]);
            ps += p.x * a_s2[2 * j] + p.y * a_s2[2 * j + 1];
            pd += p.x * a_d2[2 * j] + p.y * a_d2[2 * j + 1];
        }
        g_as2[gn] = ps;
        g_ad2[gn] = pd;
    }
}

// ---------------- Aggregation layer 2 + log_softmax (4 edges/iter) ----------------
__global__ void __launch_bounds__(256) agg2_kernel(const float* __restrict__ bias2,
                                                   float* __restrict__ out) {
    int gw = (blockIdx.x * blockDim.x + threadIdx.x) >> 5;
    int lane = threadIdx.x & 31;
    if (gw >= N_NODES) return;
    int n = gw;
    int start = g_off[n], end = g_off[n + 1];
    float adv = g_ad2[n];

    float acc0 = 0.f, acc1 = 0.f, denom = 0.f;
    int e = start;
    int s[4];
#pragma unroll
    for (int j = 0; j < 4; j++) s[j] = (e + j < end) ? g_csr[e + j] : 0;

    while (e + 3 < end) {
        int ns[4];
#pragma unroll
        for (int j = 0; j < 4; j++) ns[j] = (e + 4 + j < end) ? g_csr[e + 4 + j] : 0;
        float w = 0.f;
        if (lane < 4) {
            float v = g_as2[s[lane]] + adv;
            v = v > 0.f ? v : 0.2f * v;
            w = __expf(v);
            denom += w;
        }
#pragma unroll
        for (int j = 0; j < 4; j++) {
            float wj = __shfl_sync(0xffffffffu, w, j);
            const float* p = &g_h2[(size_t)s[j] * C2];
            acc0 += wj * p[lane];
            if (lane < 8) acc1 += wj * p[32 + lane];
        }
#pragma unroll
        for (int j = 0; j < 4; j++) s[j] = ns[j];
        e += 4;
    }
    for (int j = 0; e < end; e++, j++) {
        int sv = s[j];
        float w = 0.f;
        if (lane == 0) {
            float v = g_as2[sv] + adv;
            v = v > 0.f ? v : 0.2f * v;
            w = __expf(v);
            denom += w;
        }
        float wj = __shfl_sync(0xffffffffu, w, 0);
        const float* p = &g_h2[(size_t)sv * C2];
        acc0 += wj * p[lane];
        if (lane < 8) acc1 += wj * p[32 + lane];
    }

    denom += __shfl_xor_sync(0xffffffffu, denom, 1);
    denom += __shfl_xor_sync(0xffffffffu, denom, 2);
    float d = __shfl_sync(0xffffffffu, denom, 0) + 1e-16f;
    float r0 = acc0 / d + bias2[lane];
    float r1 = (lane < 8) ? (acc1 / d + bias2[32 + lane]) : -INFINITY;

    float mm = fmaxf(r0, r1);
#pragma unroll
    for (int o = 16; o > 0; o >>= 1)
        mm = fmaxf(mm, __shfl_xor_sync(0xffffffffu, mm, o));
    float ss = __expf(r0 - mm) + ((lane < 8) ? __expf(r1 - mm) : 0.f);
#pragma unroll
    for (int o = 16; o > 0; o >>= 1)
        ss += __shfl_xor_sync(0xffffffffu, ss, o);
    float lse = __logf(ss);

    out[(size_t)n * C2 + lane] = r0 - mm - lse;
    if (lane < 8) out[(size_t)n * C2 + 32 + lane] = r1 - mm - lse;
}

// ---------------- launch ----------------
extern "C" void kernel_launch(void* const* d_in, const int* in_sizes, int n_in,
                              void* d_out, int out_size) {
    const float* x     = (const float*)d_in[0];
    const int*   ei    = (const int*)  d_in[1];
    const float* W1    = (const float*)d_in[2];
    const float* as1   = (const float*)d_in[3];
    const float* ad1   = (const float*)d_in[4];
    const float* b1    = (const float*)d_in[5];
    const float* W2    = (const float*)d_in[6];
    const float* as2   = (const float*)d_in[7];
    const float* ad2   = (const float*)d_in[8];
    const float* b2    = (const float*)d_in[9];
    float* out = (float*)d_out;

    (void)in_sizes; (void)n_in; (void)out_size;

    zero_kernel   <<<(N_NODES + 255) / 256, 256>>>();
    fat1_kernel   <<<G1_BLOCKS + HB_BLOCKS, 256>>>(x, W1, as1, ad1, ei);  // gemm1 || hist
    scanA_kernel  <<<SC_BLOCKS, 256>>>();
    scanB_kernel  <<<1, 512>>>();
    scanC_kernel  <<<SC_BLOCKS, 256>>>();
    scatter_kernel<<<HB_BLOCKS, 256>>>(ei);

    agg1_kernel   <<<(N_NODES * 32 + 255) / 256, 256>>>(b1);
    gemm2_kernel  <<<(N_NODES + 127) / 128, 128>>>(W2, as2, ad2);
    agg2_kernel   <<<(N_NODES * 32 + 255) / 256, 256>>>(b2, out);
}

// round 11
// speedup vs baseline: 1.7745x; 1.0632x over previous
#include <cuda_runtime.h>
#include <cuda_fp16.h>
#include <math.h>

#define N_NODES 100000
#define E_IN    1600000
#define E_TOT   (E_IN + N_NODES)
#define F_IN    256
#define H1      8
#define C1      64      /* H1*F1 */
#define C2      40      /* classes */

#define G1_BLOCKS ((N_NODES + 127) / 128)          /* 782 gemm1 tiles   */
#define HB_BLOCKS ((E_TOT + 255) / 256)            /* 6641 hist chunks  */
#define SC_BLOCKS ((N_NODES + 255) / 256)          /* 391 scan blocks   */

// ---------------- scratch (static device globals; no allocation) ----------------
__device__ uint4 g_h1p[(size_t)N_NODES * 8];   // layer-1 features, fp16: 8 halves per uint4
__device__ uint4 g_h2p[(size_t)N_NODES * 5];   // layer-2 features, fp16: 40 halves = 5 uint4
__device__ float g_as1[(size_t)N_NODES * H1];
__device__ float g_ad1[(size_t)N_NODES * H1];
__device__ float g_x2 [(size_t)N_NODES * C1];
__device__ float g_as2[N_NODES];
__device__ float g_ad2[N_NODES];
__device__ int   g_deg[N_NODES];
__device__ int   g_cur[N_NODES];
__device__ int   g_off[N_NODES + 1];
__device__ int   g_csr[E_TOT];
__device__ int   g_part[SC_BLOCKS];
__device__ int   g_poff[SC_BLOCKS];

// ---------------- helpers ----------------
__device__ __forceinline__ float tf32r(float v) {
    unsigned u;
    asm("cvt.rna.tf32.f32 %0, %1;" : "=r"(u) : "f"(v));
    return __uint_as_float(u);
}
__device__ __forceinline__ void mma_tf32(float* c, const unsigned* a, const unsigned* b) {
    asm volatile(
        "mma.sync.aligned.m16n8k8.row.col.f32.tf32.tf32.f32 "
        "{%0,%1,%2,%3}, {%4,%5,%6,%7}, {%8,%9}, {%0,%1,%2,%3};\n"
        : "+f"(c[0]), "+f"(c[1]), "+f"(c[2]), "+f"(c[3])
        : "r"(a[0]), "r"(a[1]), "r"(a[2]), "r"(a[3]), "r"(b[0]), "r"(b[1]));
}
__device__ __forceinline__ unsigned long long packf2(float a, float b) {
    unsigned long long r;
    asm("mov.b64 %0, {%1, %2};" : "=l"(r) : "f"(a), "f"(b));
    return r;
}
__device__ __forceinline__ void fma2(unsigned long long& d,
                                     unsigned long long a, unsigned long long b) {
    asm("fma.rn.f32x2 %0, %1, %2, %0;" : "+l"(d) : "l"(a), "l"(b));
}
__device__ __forceinline__ float2 unpk(unsigned long long v) {
    float2 r;
    asm("mov.b64 {%0, %1}, %2;" : "=f"(r.x), "=f"(r.y) : "l"(v));
    return r;
}

// ---------------- CSR build ----------------
__global__ void zero_kernel() {
    int i = blockIdx.x * blockDim.x + threadIdx.x;
    if (i < N_NODES) { g_deg[i] = 0; g_cur[i] = 0; }
}

__global__ void scanA_kernel() {
    __shared__ int ws[8];
    int tid = threadIdx.x;
    int i = blockIdx.x * 256 + tid;
    int v = (i < N_NODES) ? g_deg[i] : 0;
    int s = v;
#pragma unroll
    for (int o = 16; o > 0; o >>= 1) s += __shfl_xor_sync(0xffffffffu, s, o);
    if ((tid & 31) == 0) ws[tid >> 5] = s;
    __syncthreads();
    if (tid < 8) {
        int t = ws[tid];
#pragma unroll
        for (int o = 4; o > 0; o >>= 1) t += __shfl_xor_sync(0xffu, t, o);
        if (tid == 0) g_part[blockIdx.x] = t;
    }
}

__global__ void scanB_kernel() {
    __shared__ int sh[512];
    int t = threadIdx.x;
    int v = (t < SC_BLOCKS) ? g_part[t] : 0;
    sh[t] = v;
    __syncthreads();
    for (int o = 1; o < 512; o <<= 1) {
        int u = (t >= o) ? sh[t - o] : 0;
        __syncthreads();
        sh[t] += u;
        __syncthreads();
    }
    if (t < SC_BLOCKS) g_poff[t] = sh[t] - v;    // exclusive
}

__global__ void scanC_kernel() {
    __shared__ int ws[8];
    int tid = threadIdx.x;
    int i = blockIdx.x * 256 + tid;
    int v = (i < N_NODES) ? g_deg[i] : 0;
    int inc = v;
#pragma unroll
    for (int o = 1; o < 32; o <<= 1) {
        int u = __shfl_up_sync(0xffffffffu, inc, o);
        if ((tid & 31) >= o) inc += u;
    }
    if ((tid & 31) == 31) ws[tid >> 5] = inc;
    __syncthreads();
    if (tid < 8) {
        int t = ws[tid];
#pragma unroll
        for (int o = 1; o < 8; o <<= 1) {
            int u = __shfl_up_sync(0xffu, t, o);
            if (tid >= o) t += u;
        }
        ws[tid] = t;
    }
    __syncthreads();
    int wbase = (tid >= 32) ? ws[(tid >> 5) - 1] : 0;
    int excl = g_poff[blockIdx.x] + wbase + inc - v;
    if (i < N_NODES) {
        g_off[i] = excl;
        if (i == N_NODES - 1) g_off[N_NODES] = excl + v;  // == E_TOT
    }
}

__global__ void scatter_kernel(const int* __restrict__ ei) {
    int i = blockIdx.x * blockDim.x + threadIdx.x;
    if (i >= E_TOT) return;
    int d, s;
    if (i < E_IN) { s = ei[i]; d = ei[E_IN + i]; }
    else          { s = i - E_IN; d = i - E_IN; }
    int p = g_off[d] + atomicAdd(&g_cur[d], 1);
    g_csr[p] = s;
}

// ---------------- fat kernel: gemm1 (tf32 mma.sync) || hist ----------------
__global__ void __launch_bounds__(256) fat1_kernel(
        const float* __restrict__ x, const float* __restrict__ W1,
        const float* __restrict__ a_s, const float* __restrict__ a_d,
        const int* __restrict__ ei) {
    __shared__ __align__(16) float smem_pool[128 * 65];
    int tid = threadIdx.x;

    if (blockIdx.x >= G1_BLOCKS) {
        int i = (blockIdx.x - G1_BLOCKS) * 256 + tid;
        if (i < E_TOT) {
            int d = (i < E_IN) ? ei[E_IN + i] : (i - E_IN);
            atomicAdd(&g_deg[d], 1);
        }
        return;
    }

    float (*Xs)[33] = (float (*)[33])smem_pool;
    float (*Ws)[64] = (float (*)[64])(smem_pool + 128 * 33);
    float (*Cs)[65] = (float (*)[65])smem_pool;

    int lane = tid & 31;
    int warp = tid >> 5;
    int rg = warp >> 1;
    int cg = warp & 1;
    int row0 = blockIdx.x * 128;

    float acc[2][4][4];
#pragma unroll
    for (int m = 0; m < 2; m++)
#pragma unroll
        for (int j = 0; j < 4; j++)
#pragma unroll
            for (int q = 0; q < 4; q++) acc[m][j][q] = 0.f;

    float4 xbuf[4];
    float4 wbuf[2];
#pragma unroll
    for (int i = 0; i < 4; i++) {
        int idx = tid + i * 256; int r = idx >> 3, q = idx & 7;
        int gr = row0 + r;
        xbuf[i] = (gr < N_NODES) ? *(const float4*)&x[(size_t)gr * F_IN + q * 4]
                                 : make_float4(0.f, 0.f, 0.f, 0.f);
    }
#pragma unroll
    for (int i = 0; i < 2; i++) {
        int idx = tid + i * 256; int r = idx >> 4, q = idx & 15;
        wbuf[i] = *(const float4*)&W1[(size_t)r * C1 + q * 4];
    }

    for (int kt = 0; kt < F_IN; kt += 32) {
#pragma unroll
        for (int i = 0; i < 4; i++) {
            int idx = tid + i * 256; int r = idx >> 3, q = idx & 7;
            Xs[r][q * 4 + 0] = tf32r(xbuf[i].x); Xs[r][q * 4 + 1] = tf32r(xbuf[i].y);
            Xs[r][q * 4 + 2] = tf32r(xbuf[i].z); Xs[r][q * 4 + 3] = tf32r(xbuf[i].w);
        }
#pragma unroll
        for (int i = 0; i < 2; i++) {
            int idx = tid + i * 256; int r = idx >> 4, q = idx & 15;
            Ws[r][q * 4 + 0] = tf32r(wbuf[i].x); Ws[r][q * 4 + 1] = tf32r(wbuf[i].y);
            Ws[r][q * 4 + 2] = tf32r(wbuf[i].z); Ws[r][q * 4 + 3] = tf32r(wbuf[i].w);
        }
        __syncthreads();

        int ktn = kt + 32;
        if (ktn < F_IN) {
#pragma unroll
            for (int i = 0; i < 4; i++) {
                int idx = tid + i * 256; int r = idx >> 3, q = idx & 7;
                int gr = row0 + r;
                xbuf[i] = (gr < N_NODES) ? *(const float4*)&x[(size_t)gr * F_IN + ktn + q * 4]
                                         : make_float4(0.f, 0.f, 0.f, 0.f);
            }
#pragma unroll
            for (int i = 0; i < 2; i++) {
                int idx = tid + i * 256; int r = idx >> 4, q = idx & 15;
                wbuf[i] = *(const float4*)&W1[(size_t)(ktn + r) * C1 + q * 4];
            }
        }

#pragma unroll
        for (int ks = 0; ks < 4; ks++) {
            int k0 = ks * 8;
            unsigned afr[2][4];
#pragma unroll
            for (int m = 0; m < 2; m++) {
                int R = rg * 32 + m * 16;
                afr[m][0] = __float_as_uint(Xs[R + (lane >> 2)][k0 + (lane & 3)]);
                afr[m][1] = __float_as_uint(Xs[R + (lane >> 2) + 8][k0 + (lane & 3)]);
                afr[m][2] = __float_as_uint(Xs[R + (lane >> 2)][k0 + (lane & 3) + 4]);
                afr[m][3] = __float_as_uint(Xs[R + (lane >> 2) + 8][k0 + (lane & 3) + 4]);
            }
            unsigned bfr[4][2];
#pragma unroll
            for (int j = 0; j < 4; j++) {
                int Cb = cg * 32 + j * 8;
                bfr[j][0] = __float_as_uint(Ws[k0 + (lane & 3)][Cb + (lane >> 2)]);
                bfr[j][1] = __float_as_uint(Ws[k0 + (lane & 3) + 4][Cb + (lane >> 2)]);
            }
#pragma unroll
            for (int m = 0; m < 2; m++)
#pragma unroll
                for (int j = 0; j < 4; j++)
                    mma_tf32(acc[m][j], afr[m], bfr[j]);
        }
        __syncthreads();
    }

#pragma unroll
    for (int m = 0; m < 2; m++) {
        int R = rg * 32 + m * 16 + (lane >> 2);
#pragma unroll
        for (int j = 0; j < 4; j++) {
            int Cb = cg * 32 + j * 8 + 2 * (lane & 3);
            Cs[R][Cb]         = acc[m][j][0];
            Cs[R][Cb + 1]     = acc[m][j][1];
            Cs[R + 8][Cb]     = acc[m][j][2];
            Cs[R + 8][Cb + 1] = acc[m][j][3];
        }
    }
    __syncthreads();

    {
        int r = tid >> 1;
        int half = tid & 1;
        int gr = row0 + r;
        if (gr < N_NODES) {
            int c0 = half * 32;
            float f[32];
#pragma unroll
            for (int q = 0; q < 32; q++) f[q] = Cs[r][c0 + q];
#pragma unroll
            for (int h = 0; h < 4; h++) {
                int head = half * 4 + h;
                float ps = 0.f, pd = 0.f;
#pragma unroll
                for (int q = 0; q < 8; q++) {
                    ps += f[h * 8 + q] * a_s[head * 8 + q];
                    pd += f[h * 8 + q] * a_d[head * 8 + q];
                }
                g_as1[gr * H1 + head] = ps;
                g_ad1[gr * H1 + head] = pd;
            }
#pragma unroll
            for (int u = 0; u < 4; u++) {
                __half2 hh[4];
#pragma unroll
                for (int q = 0; q < 4; q++)
                    hh[q] = __floats2half2_rn(f[u * 8 + 2 * q], f[u * 8 + 2 * q + 1]);
                g_h1p[(size_t)gr * 8 + half * 4 + u] = *(uint4*)hh;
            }
        }
    }
}

// ---------------- Aggregation layer 1 (warp per dst; fp16 gather; 4 edges/iter) ----------------
// Lane owns half2 #lane (features 2*lane, 2*lane+1) -> head hA = lane>>2.
// Weight duty: lane computes w for edge slot (lane>>3), head (lane&7).
__global__ void __launch_bounds__(256) agg1_kernel(const float* __restrict__ bias1) {
    int gw = (blockIdx.x * blockDim.x + threadIdx.x) >> 5;
    int lane = threadIdx.x & 31;
    if (gw >= N_NODES) return;
    int n = gw;
    int start = g_off[n], end = g_off[n + 1];

    int head = lane & 7;
    int slot = lane >> 3;
    int hA = lane >> 2;
    float adv = g_ad1[n * H1 + head];

    float accLo = 0.f, accHi = 0.f, denom = 0.f;
    int e = start;
    int s[4];
#pragma unroll
    for (int j = 0; j < 4; j++) s[j] = (e + j < end) ? g_csr[e + j] : 0;

    while (e + 3 < end) {
        int ns[4];
#pragma unroll
        for (int j = 0; j < 4; j++) ns[j] = (e + 4 + j < end) ? g_csr[e + 4 + j] : 0;
        float v = g_as1[s[slot] * H1 + head] + adv;
        v = v > 0.f ? v : 0.2f * v;
        float w = __expf(v);
        denom += w;
#pragma unroll
        for (int j = 0; j < 4; j++) {
            float wj = __shfl_sync(0xffffffffu, w, j * 8 + hA);
            __half2 h = ((const __half2*)&g_h1p[(size_t)s[j] * 8])[lane];
            float2 f = __half22float2(h);
            accLo += wj * f.x;
            accHi += wj * f.y;
        }
#pragma unroll
        for (int j = 0; j < 4; j++) s[j] = ns[j];
        e += 4;
    }
    int rem = end - e;           // 0..3, uniform per warp
    if (rem > 0) {
        float w = 0.f;
        if (slot < rem) {
            float v = g_as1[s[slot] * H1 + head] + adv;
            v = v > 0.f ? v : 0.2f * v;
            w = __expf(v);
            denom += w;
        }
        for (int j = 0; j < rem; j++) {
            float wj = __shfl_sync(0xffffffffu, w, j * 8 + hA);
            __half2 h = ((const __half2*)&g_h1p[(size_t)s[j] * 8])[lane];
            float2 f = __half22float2(h);
            accLo += wj * f.x;
            accHi += wj * f.y;
        }
    }

    // fold slot partials: after xor8+xor16 every lane holds total for head lane&7
    denom += __shfl_xor_sync(0xffffffffu, denom, 8);
    denom += __shfl_xor_sync(0xffffffffu, denom, 16);
    float dA = __shfl_sync(0xffffffffu, denom, hA) + 1e-16f;
    float oLo = accLo / dA + bias1[2 * lane];
    float oHi = accHi / dA + bias1[2 * lane + 1];
    oLo = oLo > 0.f ? oLo : expm1f(oLo);
    oHi = oHi > 0.f ? oHi : expm1f(oHi);
    *(float2*)&g_x2[(size_t)n * C1 + 2 * lane] = make_float2(oLo, oHi);
}

// ---------------- GEMM2: thread-per-node, fp16 packed output ----------------
__global__ void __launch_bounds__(128) gemm2_kernel(
        const float* __restrict__ W2,
        const float* __restrict__ a_s2, const float* __restrict__ a_d2) {
    __shared__ float Ws[C1][C2];
    __shared__ float Xs[128][65];
    int tid = threadIdx.x;
    int n0 = blockIdx.x * 128;
    int gn = n0 + tid;

    for (int i = tid; i < C1 * C2; i += 128) ((float*)Ws)[i] = W2[i];
#pragma unroll
    for (int i = 0; i < 16; i++) {
        int idx = tid + i * 128; int r = idx >> 4, q = idx & 15;
        int gr = n0 + r;
        float4 v = (gr < N_NODES) ? *(const float4*)&g_x2[(size_t)gr * C1 + q * 4]
                                  : make_float4(0.f, 0.f, 0.f, 0.f);
        Xs[r][q * 4 + 0] = v.x; Xs[r][q * 4 + 1] = v.y;
        Xs[r][q * 4 + 2] = v.z; Xs[r][q * 4 + 3] = v.w;
    }
    __syncthreads();

    unsigned long long acc2[20];
#pragma unroll
    for (int j = 0; j < 20; j++) acc2[j] = 0ull;

    if (gn < N_NODES) {
#pragma unroll 4
        for (int k = 0; k < C1; k++) {
            float a = Xs[tid][k];
            unsigned long long ap = packf2(a, a);
            const unsigned long long* wp = (const unsigned long long*)&Ws[k][0];
#pragma unroll
            for (int j = 0; j < 20; j++) fma2(acc2[j], ap, wp[j]);
        }
        float ps = 0.f, pd = 0.f;
        __half2 hh[20];
#pragma unroll
        for (int j = 0; j < 20; j++) {
            float2 p = unpk(acc2[j]);
            hh[j] = __floats2half2_rn(p.x, p.y);
            ps += p.x * a_s2[2 * j] + p.y * a_s2[2 * j + 1];
            pd += p.x * a_d2[2 * j] + p.y * a_d2[2 * j + 1];
        }
        const uint4* hv = (const uint4*)hh;
#pragma unroll
        for (int u = 0; u < 5; u++) g_h2p[(size_t)gn * 5 + u] = hv[u];
        g_as2[gn] = ps;
        g_ad2[gn] = pd;
    }
}

// ---------------- Aggregation layer 2 + log_softmax (fp16 rows; 4 edges/iter) ----------------
// Lanes 0-19 own half2 #lane = classes (2*lane, 2*lane+1). Lanes 0-3 compute weights.
__global__ void __launch_bounds__(256) agg2_kernel(const float* __restrict__ bias2,
                                                   float* __restrict__ out) {
    int gw = (blockIdx.x * blockDim.x + threadIdx.x) >> 5;
    int lane = threadIdx.x & 31;
    if (gw >= N_NODES) return;
    int n = gw;
    int start = g_off[n], end = g_off[n + 1];
    float adv = g_ad2[n];

    float accLo = 0.f, accHi = 0.f, denom = 0.f;
    int e = start;
    int s[4];
#pragma unroll
    for (int j = 0; j < 4; j++) s[j] = (e + j < end) ? g_csr[e + j] : 0;

    while (e + 3 < end) {
        int ns[4];
#pragma unroll
        for (int j = 0; j < 4; j++) ns[j] = (e + 4 + j < end) ? g_csr[e + 4 + j] : 0;
        float w = 0.f;
        if (lane < 4) {
            float v = g_as2[s[lane]] + adv;
            v = v > 0.f ? v : 0.2f * v;
            w = __expf(v);
            denom += w;
        }
#pragma unroll
        for (int j = 0; j < 4; j++) {
            float wj = __shfl_sync(0xffffffffu, w, j);
            if (lane < 20) {
                __half2 h = ((const __half2*)&g_h2p[(size_t)s[j] * 5])[lane];
                float2 f = __half22float2(h);
                accLo += wj * f.x;
                accHi += wj * f.y;
            }
        }
#pragma unroll
        for (int j = 0; j < 4; j++) s[j] = ns[j];
        e += 4;
    }
    int rem = end - e;
    if (rem > 0) {
        float w = 0.f;
        if (lane < rem) {
            float v = g_as2[s[lane]] + adv;
            v = v > 0.f ? v : 0.2f * v;
            w = __expf(v);
            denom += w;
        }
        for (int j = 0; j < rem; j++) {
            float wj = __shfl_sync(0xffffffffu, w, j);
            if (lane < 20) {
                __half2 h = ((const __half2*)&g_h2p[(size_t)s[j] * 5])[lane];
                float2 f = __half22float2(h);
                accLo += wj * f.x;
                accHi += wj * f.y;
            }
        }
    }

    denom += __shfl_xor_sync(0xffffffffu, denom, 1);
    denom += __shfl_xor_sync(0xffffffffu, denom, 2);
    float d = __shfl_sync(0xffffffffu, denom, 0) + 1e-16f;

    float r0 = -INFINITY, r1 = -INFINITY;
    if (lane < 20) {
        r0 = accLo / d + bias2[2 * lane];
        r1 = accHi / d + bias2[2 * lane + 1];
    }
    float mm = fmaxf(r0, r1);
#pragma unroll
    for (int o = 16; o > 0; o >>= 1)
        mm = fmaxf(mm, __shfl_xor_sync(0xffffffffu, mm, o));
    float ss = (lane < 20) ? (__expf(r0 - mm) + __expf(r1 - mm)) : 0.f;
#pragma unroll
    for (int o = 16; o > 0; o >>= 1)
        ss += __shfl_xor_sync(0xffffffffu, ss, o);
    float lse = __logf(ss);

    if (lane < 20)
        *(float2*)&out[(size_t)n * C2 + 2 * lane] = make_float2(r0 - mm - lse, r1 - mm - lse);
}

// ---------------- launch ----------------
extern "C" void kernel_launch(void* const* d_in, const int* in_sizes, int n_in,
                              void* d_out, int out_size) {
    const float* x     = (const float*)d_in[0];
    const int*   ei    = (const int*)  d_in[1];
    const float* W1    = (const float*)d_in[2];
    const float* as1   = (const float*)d_in[3];
    const float* ad1   = (const float*)d_in[4];
    const float* b1    = (const float*)d_in[5];
    const float* W2    = (const float*)d_in[6];
    const float* as2   = (const float*)d_in[7];
    const float* ad2   = (const float*)d_in[8];
    const float* b2    = (const float*)d_in[9];
    float* out = (float*)d_out;

    (void)in_sizes; (void)n_in; (void)out_size;

    zero_kernel   <<<(N_NODES + 255) / 256, 256>>>();
    fat1_kernel   <<<G1_BLOCKS + HB_BLOCKS, 256>>>(x, W1, as1, ad1, ei);  // gemm1 || hist
    scanA_kernel  <<<SC_BLOCKS, 256>>>();
    scanB_kernel  <<<1, 512>>>();
    scanC_kernel  <<<SC_BLOCKS, 256>>>();
    scatter_kernel<<<HB_BLOCKS, 256>>>(ei);

    agg1_kernel   <<<(N_NODES * 32 + 255) / 256, 256>>>(b1);
    gemm2_kernel  <<<(N_NODES + 127) / 128, 128>>>(W2, as2, ad2);
    agg2_kernel   <<<(N_NODES * 32 + 255) / 256, 256>>>(b2, out);
}